// round 15
// baseline (speedup 1.0000x reference)
#include <cuda_runtime.h>
#include <cuda_bf16.h>
#include <cstdint>

#define N_RAYS_C 16384
#define RAYS_PER_BLK 4
#define NBLK (N_RAYS_C / RAYS_PER_BLK)

// ---- smem byte offsets ----
#define A32HI 0
#define A32LO 10240
#define BOFF  20480
#define B1HI  (BOFF + 0)
#define B1LO  (BOFF + 5120)
#define B2HI  (BOFF + 10240)
#define B2LO  (BOFF + 12544)
#define B3HI  (BOFF + 14848)
#define B3LO  (BOFF + 19968)
#define B4HI  (BOFF + 25088)
#define B4LO  (BOFF + 26240)
#define BBYTES 27392
#define BIAS1 (BOFF + BBYTES)    // 64 f
#define BIAS2 (BIAS1 + 256)      // 16 f
#define WC1SH (BIAS2 + 64)       // 4 x 64 f (Wc1 rows 15..18)
#define BC1S  (WC1SH + 1024)     // 64 f (bc1 cache)
#define BIAS3 (BC1S + 256)       // 4 warps x 64 f (per-warp fused bias)
#define SIGO  (BIAS3 + 1024)     // 128 f
#define RGBO  (SIGO + 512)       // 128 x 16B
#define SCANW (RGBO + 2048)
#define PARTO (SCANW + 16)
#define SMEM_DYN 54272

#define S32 80
#define S64 144

__device__ __align__(16) unsigned char g_B[BBYTES];
__device__ float g_params[8];   // [1..3] = bc2

// ---- helpers ----
__device__ __forceinline__ uint32_t smem_u32(const void* p) {
    uint32_t a;
    asm("{ .reg .u64 t; cvta.to.shared.u64 t, %1; cvt.u32.u64 %0, t; }" : "=r"(a) : "l"(p));
    return a;
}
__device__ __forceinline__ void sts32(uint32_t a, uint32_t v) {
    asm volatile("st.shared.b32 [%0], %1;" :: "r"(a), "r"(v) : "memory");
}
__device__ __forceinline__ void sts128(uint32_t a, uint32_t v0, uint32_t v1,
                                       uint32_t v2, uint32_t v3) {
    asm volatile("st.shared.v4.b32 [%0], {%1,%2,%3,%4};"
                 :: "r"(a), "r"(v0), "r"(v1), "r"(v2), "r"(v3) : "memory");
}
__device__ __forceinline__ uint32_t lds32(uint32_t a) {
    uint32_t v; asm volatile("ld.shared.b32 %0, [%1];" : "=r"(v) : "r"(a)); return v;
}
__device__ __forceinline__ float ldsf(uint32_t a) { return __uint_as_float(lds32(a)); }
__device__ __forceinline__ float2 ldsf2(uint32_t a) {
    float2 v;
    asm volatile("ld.shared.v2.f32 {%0,%1}, [%2];" : "=f"(v.x), "=f"(v.y) : "r"(a));
    return v;
}
__device__ __forceinline__ void stsf(uint32_t a, float v) { sts32(a, __float_as_uint(v)); }

__device__ __forceinline__ void ldm_x4(uint32_t addr, uint32_t* r) {
    asm volatile("ldmatrix.sync.aligned.m8n8.x4.shared.b16 {%0,%1,%2,%3}, [%4];"
        : "=r"(r[0]), "=r"(r[1]), "=r"(r[2]), "=r"(r[3]) : "r"(addr));
}
__device__ __forceinline__ void ldm_x2(uint32_t addr, uint32_t* r) {
    asm volatile("ldmatrix.sync.aligned.m8n8.x2.shared.b16 {%0,%1}, [%2];"
        : "=r"(r[0]), "=r"(r[1]) : "r"(addr));
}

// pack f32 pair -> bf16x2 hi + residual lo; residual via bit-extract of hi
__device__ __forceinline__ void split2(float v0, float v1, uint32_t& hi, uint32_t& lo) {
    asm("cvt.rn.bf16x2.f32 %0, %1, %2;" : "=r"(hi) : "f"(v1), "f"(v0));
    const float r0 = v0 - __uint_as_float(hi << 16);
    const float r1 = v1 - __uint_as_float(hi & 0xffff0000u);
    asm("cvt.rn.bf16x2.f32 %0, %1, %2;" : "=r"(lo) : "f"(r1), "f"(r0));
}

__device__ __forceinline__ void mma16816(float* d,
        uint32_t a0, uint32_t a1, uint32_t a2, uint32_t a3,
        uint32_t b0, uint32_t b1) {
    asm volatile("mma.sync.aligned.m16n8k16.row.col.f32.bf16.bf16.f32 "
        "{%0,%1,%2,%3}, {%4,%5,%6,%7}, {%8,%9}, {%0,%1,%2,%3};"
        : "+f"(d[0]), "+f"(d[1]), "+f"(d[2]), "+f"(d[3])
        : "r"(a0), "r"(a1), "r"(a2), "r"(a3), "r"(b0), "r"(b1));
}
#define MMA(acc, a, b0, b1) mma16816(acc, (a)[0], (a)[1], (a)[2], (a)[3], b0, b1)

// ---- setup: build hi/lo weight image in [n][k]-padded layouts ----
__global__ void k_setup(const float* __restrict__ W1, const float* __restrict__ W2,
                        const float* __restrict__ Wc1, const float* __restrict__ Wc2,
                        const float* __restrict__ bc2) {
    const int tid = blockIdx.x * blockDim.x + threadIdx.x;
    if (tid == 0) { g_params[1] = bc2[0]; g_params[2] = bc2[1]; g_params[3] = bc2[2]; }
    const int n1 = 64 * 40, n2 = 16 * 72, n3 = 64 * 40, n4 = 8 * 72;
    for (int i = tid; i < n1 + n2 + n3 + n4; i += blockDim.x * gridDim.x) {
        float v; int hiOff, loOff;
        if (i < n1) {
            int n = i / 40, k = i % 40;
            v = (k < 27) ? W1[k * 64 + n] : 0.0f;
            hiOff = (B1HI - BOFF) + i * 2; loOff = (B1LO - BOFF) + i * 2;
        } else if (i < n1 + n2) {
            int j = i - n1, n = j / 72, k = j % 72;
            v = (k < 64) ? W2[k * 16 + n] : 0.0f;
            hiOff = (B2HI - BOFF) + j * 2; loOff = (B2LO - BOFF) + j * 2;
        } else if (i < n1 + n2 + n3) {
            int j = i - n1 - n2, n = j / 40, k = j % 40;
            v = (k >= 1 && k < 16) ? Wc1[(k - 1) * 64 + n] : 0.0f;   // ynm folded into bias
            hiOff = (B3HI - BOFF) + j * 2; loOff = (B3LO - BOFF) + j * 2;
        } else {
            int j = i - n1 - n2 - n3, n = j / 72, k = j % 72;
            v = (n < 3 && k < 64) ? Wc2[k * 3 + n] : 0.0f;
            hiOff = (B4HI - BOFF) + j * 2; loOff = (B4LO - BOFF) + j * 2;
        }
        __nv_bfloat16 hi = __float2bfloat16(v);
        __nv_bfloat16 lo = __float2bfloat16(v - __bfloat162float(hi));
        *(__nv_bfloat16*)(g_B + hiOff) = hi;
        *(__nv_bfloat16*)(g_B + loOff) = lo;
    }
}

// ---- render: 128 threads, 4 warps x M=32 rows, 4 rays sequential ----
__global__ void __launch_bounds__(128, 4) nerf_mma8_kernel(
    const float* __restrict__ rays_o, const float* __restrict__ rays_d,
    const float* __restrict__ tnoise, const float* __restrict__ aabb,
    const float* __restrict__ b1, const float* __restrict__ b2,
    const float* __restrict__ bc1, const float* __restrict__ Wc1,
    float* __restrict__ out) {
    extern __shared__ __align__(16) unsigned char sm[];
    const uint32_t base = smem_u32(sm);
    const int tid = threadIdx.x, lane = tid & 31, wid = tid >> 5;
    const int g = lane >> 2, tg = lane & 3;
    const int m0 = wid * 32;

    // prologue: weights + biases + Wc1 SH rows + bc1 cache
    {
        const int4* src = (const int4*)g_B;
        int4* dst = (int4*)(sm + BOFF);
        for (int i = tid; i < BBYTES / 16; i += 128) dst[i] = src[i];
        if (tid < 64) stsf(base + BIAS1 + 4 * tid, b1[tid]);
        if (tid < 16) stsf(base + BIAS2 + 4 * tid, b2[tid]);
        if (tid >= 64) stsf(base + BC1S + 4 * (tid - 64), bc1[tid - 64]);
        for (int i = tid; i < 256; i += 128)
            stsf(base + WC1SH + 4 * i, Wc1[15 * 64 + i]);
    }
    const float ax0 = aabb[0], ay0 = aabb[1], az0 = aabb[2];
    const float ax1 = aabb[3], ay1 = aabb[4], az1 = aabb[5];
    const float p1 = g_params[1], p2 = g_params[2], p3 = g_params[3];
    __syncthreads();

    // per-lane ldmatrix address components
    const uint32_t arow = (uint32_t)((lane & 7) + ((lane >> 3) & 1) * 8);
    const uint32_t ak   = (uint32_t)(((lane >> 4) & 1) * 16);
    const uint32_t bn32 = (uint32_t)(((lane & 7) + ((lane >> 4) & 1) * 8) * S32
                                     + ((lane >> 3) & 1) * 16);
    const uint32_t bn64 = (uint32_t)(((lane & 7) + ((lane >> 4) & 1) * 8) * S64
                                     + ((lane >> 3) & 1) * 16);
    const uint32_t bn8  = (uint32_t)((lane & 7) * S64 + ((lane >> 3) & 1) * 16);
    const uint32_t bias3w = base + BIAS3 + (uint32_t)wid * 256u;

    for (int rr = 0; rr < RAYS_PER_BLK; ++rr) {
        const int ray = blockIdx.x * RAYS_PER_BLK + rr;

        // tnoise first: overlap LDG latency with the AABB math below
        const float n0 = tnoise[tid * N_RAYS_C + ray];
        const float n1 = (tid < 127) ? tnoise[(tid + 1) * N_RAYS_C + ray] : 0.0f;

        // ---- ray setup (thread = sample row tid) ----
        const float ox = rays_o[3 * ray], oy = rays_o[3 * ray + 1], oz = rays_o[3 * ray + 2];
        const float dx = rays_d[3 * ray], dy = rays_d[3 * ray + 1], dz = rays_d[3 * ray + 2];
        const float ix = 1.0f / dx, iy = 1.0f / dy, iz = 1.0f / dz;
        const float t0x = (ax0 - ox) * ix, t1x = (ax1 - ox) * ix;
        const float t0y = (ay0 - oy) * iy, t1y = (ay1 - oy) * iy;
        const float t0z = (az0 - oz) * iz, t1z = (az1 - oz) * iz;
        float tn = fmaxf(fmaxf(fminf(t0x, t1x), fminf(t0y, t1y)), fminf(t0z, t1z));
        tn = fmaxf(tn, 0.0f);
        float tf = fminf(fminf(fmaxf(t0x, t1x), fmaxf(t0y, t1y)), fmaxf(t0z, t1z));
        float act;
        if (tf > tn) { act = 1.0f; } else { act = 0.0f; tn = 0.0f; tf = 0.0f; }
        const float span = tf - tn;
        const float dnorm = sqrtf(dx * dx + dy * dy + dz * dz);

        const float ts  = tn + span * (((float)tid + n0) * (1.0f / 128.0f));
        const float ts1 = tn + span * (((float)tid + 1.0f + n1) * (1.0f / 128.0f));
        const float delta = (tid < 127) ? (ts1 - ts) : (tf * 10.0f - ts);

        const float idn = 1.0f / dnorm;
        const float c1 = 0.4886025119029199f;
        const float y0 = 0.28209479177387814f, y1 = c1 * dy * idn;
        const float y2 = c1 * dz * idn,        y3 = c1 * dx * idn;

        // per-WARP fused color-layer bias: bc1 + ynm @ Wc1[15:19] (fp32, 2 entries/lane)
        #pragma unroll
        for (int h = 0; h < 2; ++h) {
            const int j = lane + 32 * h;
            const float s = ldsf(base + BC1S + 4 * j)
                          + y0 * ldsf(base + WC1SH + 4 * j)
                          + y1 * ldsf(base + WC1SH + 4 * (64 + j))
                          + y2 * ldsf(base + WC1SH + 4 * (128 + j))
                          + y3 * ldsf(base + WC1SH + 4 * (192 + j));
            stsf(bias3w + 4 * j, s);
        }

        {   // posenc -> packed regs -> A32 row tid via 4+4 STS.128
            float e[28];
            const float px = ox + ts * dx, py = oy + ts * dy, pz = oz + ts * dz;
            const float xnx = 2.0f * (px - ax0) / (ax1 - ax0) - 1.0f;
            const float xny = 2.0f * (py - ay0) / (ay1 - ay0) - 1.0f;
            const float xnz = 2.0f * (pz - az0) / (az1 - az0) - 1.0f;
            e[0] = xnx; e[1] = xny; e[2] = xnz;
            float f = 3.14159265358979323846f;
            #pragma unroll
            for (int k = 0; k < 4; ++k) {
                float sx, cx, sy, cy, sz, cz;
                __sincosf(f * xnx, &sx, &cx);
                __sincosf(f * xny, &sy, &cy);
                __sincosf(f * xnz, &sz, &cz);
                e[3 + 6 * k + 0] = sx; e[3 + 6 * k + 1] = sy; e[3 + 6 * k + 2] = sz;
                e[6 + 6 * k + 0] = cx; e[6 + 6 * k + 1] = cy; e[6 + 6 * k + 2] = cz;
                f *= 2.0f;
            }
            e[27] = 0.0f;
            uint32_t hp[16], lp[16];
            #pragma unroll
            for (int p = 0; p < 14; ++p) split2(e[2 * p], e[2 * p + 1], hp[p], lp[p]);
            hp[14] = hp[15] = 0u; lp[14] = lp[15] = 0u;   // cols 28..31 zero
            const uint32_t rb = (uint32_t)tid * S32;
            #pragma unroll
            for (int q = 0; q < 4; ++q) {
                sts128(base + A32HI + rb + 16 * q, hp[4 * q], hp[4 * q + 1], hp[4 * q + 2], hp[4 * q + 3]);
                sts128(base + A32LO + rb + 16 * q, lp[4 * q], lp[4 * q + 1], lp[4 * q + 2], lp[4 * q + 3]);
            }
        }
        __syncwarp();   // A32 rows + BIAS3 are warp-local

        float acc[2][8][4];
        // ---- stage 1: posenc @ W1 (K32,N64) ----
        {
            uint32_t a1h[2][2][4], a1l[2][2][4];
            #pragma unroll
            for (int mt = 0; mt < 2; ++mt) {
                const uint32_t ao = (uint32_t)((m0 + 16 * mt) * S32) + arow * S32 + ak;
                #pragma unroll
                for (int kb = 0; kb < 2; ++kb) {
                    ldm_x4(base + A32HI + ao + kb * 32, a1h[mt][kb]);
                    ldm_x4(base + A32LO + ao + kb * 32, a1l[mt][kb]);
                }
            }
            #pragma unroll
            for (int mt = 0; mt < 2; ++mt)
                #pragma unroll
                for (int nt = 0; nt < 8; ++nt)
                    acc[mt][nt][0] = acc[mt][nt][1] = acc[mt][nt][2] = acc[mt][nt][3] = 0.f;
            #pragma unroll
            for (int np = 0; np < 4; ++np) {
                #pragma unroll
                for (int kb = 0; kb < 2; ++kb) {
                    uint32_t bh[4], bl[4];
                    const uint32_t bo = bn32 + (uint32_t)(np * 16 * S32) + kb * 32;
                    ldm_x4(base + B1HI + bo, bh);
                    #pragma unroll
                    for (int mt = 0; mt < 2; ++mt) {
                        MMA(acc[mt][2 * np],     a1h[mt][kb], bh[0], bh[1]);
                        MMA(acc[mt][2 * np + 1], a1h[mt][kb], bh[2], bh[3]);
                        MMA(acc[mt][2 * np],     a1l[mt][kb], bh[0], bh[1]);
                        MMA(acc[mt][2 * np + 1], a1l[mt][kb], bh[2], bh[3]);
                    }
                    ldm_x4(base + B1LO + bo, bl);
                    #pragma unroll
                    for (int mt = 0; mt < 2; ++mt) {
                        MMA(acc[mt][2 * np],     a1h[mt][kb], bl[0], bl[1]);
                        MMA(acc[mt][2 * np + 1], a1h[mt][kb], bl[2], bl[3]);
                    }
                }
            }
        }

        // ---- epilogue 1: bias+relu -> stage2 A frags (registers) ----
        uint32_t f2h[2][4][4], f2l[2][4][4];
        #pragma unroll
        for (int nt = 0; nt < 8; ++nt) {
            const int c = nt * 8 + tg * 2;
            const float2 bb = ldsf2(base + BIAS1 + 4 * c);
            const int kb = nt >> 1, hb = (nt & 1) * 2;
            #pragma unroll
            for (int mt = 0; mt < 2; ++mt) {
                float* d = acc[mt][nt];
                split2(fmaxf(d[0] + bb.x, 0.f), fmaxf(d[1] + bb.y, 0.f),
                       f2h[mt][kb][hb], f2l[mt][kb][hb]);
                split2(fmaxf(d[2] + bb.x, 0.f), fmaxf(d[3] + bb.y, 0.f),
                       f2h[mt][kb][hb + 1], f2l[mt][kb][hb + 1]);
            }
        }

        // ---- stage 2: h @ W2 (K64,N16) ----
        #pragma unroll
        for (int mt = 0; mt < 2; ++mt)
            #pragma unroll
            for (int nt = 0; nt < 2; ++nt)
                acc[mt][nt][0] = acc[mt][nt][1] = acc[mt][nt][2] = acc[mt][nt][3] = 0.f;
        #pragma unroll
        for (int kb = 0; kb < 4; ++kb) {
            uint32_t bh[4], bl[4];
            ldm_x4(base + B2HI + bn64 + kb * 32, bh);
            #pragma unroll
            for (int mt = 0; mt < 2; ++mt) {
                MMA(acc[mt][0], f2h[mt][kb], bh[0], bh[1]);
                MMA(acc[mt][1], f2h[mt][kb], bh[2], bh[3]);
                MMA(acc[mt][0], f2l[mt][kb], bh[0], bh[1]);
                MMA(acc[mt][1], f2l[mt][kb], bh[2], bh[3]);
            }
            ldm_x4(base + B2LO + bn64 + kb * 32, bl);
            #pragma unroll
            for (int mt = 0; mt < 2; ++mt) {
                MMA(acc[mt][0], f2h[mt][kb], bl[0], bl[1]);
                MMA(acc[mt][1], f2h[mt][kb], bl[2], bl[3]);
            }
        }

        // ---- epilogue 2: sigma + stage3 A frags (K=16) ----
        uint32_t a3h[2][4], a3l[2][4];
        #pragma unroll
        for (int nt = 0; nt < 2; ++nt) {
            const int c = nt * 8 + tg * 2;
            const float2 bb = ldsf2(base + BIAS2 + 4 * c);
            const int hb = nt * 2;
            #pragma unroll
            for (int mt = 0; mt < 2; ++mt) {
                float* d = acc[mt][nt];
                const float v0 = d[0] + bb.x, v1 = d[1] + bb.y;
                const float v2 = d[2] + bb.x, v3 = d[3] + bb.y;
                split2(v0, v1, a3h[mt][hb], a3l[mt][hb]);
                split2(v2, v3, a3h[mt][hb + 1], a3l[mt][hb + 1]);
                if (nt == 0 && tg == 0) {
                    stsf(base + SIGO + 4 * (m0 + 16 * mt + g), v0);
                    stsf(base + SIGO + 4 * (m0 + 16 * mt + g + 8), v2);
                }
            }
        }

        // ---- stage 3: feat @ Wc1[0:15] (K16,N64) ----
        #pragma unroll
        for (int mt = 0; mt < 2; ++mt)
            #pragma unroll
            for (int nt = 0; nt < 8; ++nt)
                acc[mt][nt][0] = acc[mt][nt][1] = acc[mt][nt][2] = acc[mt][nt][3] = 0.f;
        #pragma unroll
        for (int np = 0; np < 4; ++np) {
            uint32_t bh[4], bl[4];
            const uint32_t bo = bn32 + (uint32_t)(np * 16 * S32);
            ldm_x4(base + B3HI + bo, bh);
            #pragma unroll
            for (int mt = 0; mt < 2; ++mt) {
                MMA(acc[mt][2 * np],     a3h[mt], bh[0], bh[1]);
                MMA(acc[mt][2 * np + 1], a3h[mt], bh[2], bh[3]);
                MMA(acc[mt][2 * np],     a3l[mt], bh[0], bh[1]);
                MMA(acc[mt][2 * np + 1], a3l[mt], bh[2], bh[3]);
            }
            ldm_x4(base + B3LO + bo, bl);
            #pragma unroll
            for (int mt = 0; mt < 2; ++mt) {
                MMA(acc[mt][2 * np],     a3h[mt], bl[0], bl[1]);
                MMA(acc[mt][2 * np + 1], a3h[mt], bl[2], bl[3]);
            }
        }

        // ---- epilogue 3: (per-warp fused bias)+relu -> stage4 A frags ----
        #pragma unroll
        for (int nt = 0; nt < 8; ++nt) {
            const int c = nt * 8 + tg * 2;
            const float2 bb = ldsf2(bias3w + 4 * c);
            const int kb = nt >> 1, hb = (nt & 1) * 2;
            #pragma unroll
            for (int mt = 0; mt < 2; ++mt) {
                float* d = acc[mt][nt];
                split2(fmaxf(d[0] + bb.x, 0.f), fmaxf(d[1] + bb.y, 0.f),
                       f2h[mt][kb][hb], f2l[mt][kb][hb]);
                split2(fmaxf(d[2] + bb.x, 0.f), fmaxf(d[3] + bb.y, 0.f),
                       f2h[mt][kb][hb + 1], f2l[mt][kb][hb + 1]);
            }
        }

        // ---- stage 4: hc @ Wc2 (K64,N8) ----
        float a4[2][4];
        a4[0][0] = a4[0][1] = a4[0][2] = a4[0][3] = 0.f;
        a4[1][0] = a4[1][1] = a4[1][2] = a4[1][3] = 0.f;
        #pragma unroll
        for (int kb = 0; kb < 4; ++kb) {
            uint32_t bh[2], bl[2];
            ldm_x2(base + B4HI + bn8 + kb * 32, bh);
            #pragma unroll
            for (int mt = 0; mt < 2; ++mt) {
                MMA(a4[mt], f2h[mt][kb], bh[0], bh[1]);
                MMA(a4[mt], f2l[mt][kb], bh[0], bh[1]);
            }
            ldm_x2(base + B4LO + bn8 + kb * 32, bl);
            #pragma unroll
            for (int mt = 0; mt < 2; ++mt)
                MMA(a4[mt], f2h[mt][kb], bl[0], bl[1]);
        }
        if (tg < 2) {
            #pragma unroll
            for (int mt = 0; mt < 2; ++mt) {
                const int rA = m0 + 16 * mt + g, rB = rA + 8;
                stsf(base + RGBO + rA * 16 + tg * 8,     a4[mt][0]);
                stsf(base + RGBO + rA * 16 + tg * 8 + 4, a4[mt][1]);
                stsf(base + RGBO + rB * 16 + tg * 8,     a4[mt][2]);
                stsf(base + RGBO + rB * 16 + tg * 8 + 4, a4[mt][3]);
            }
        }
        __syncwarp();   // SIGO/RGBO rows are warp-local

        // ---- transmittance scan + composite (thread = sample tid) ----
        const float sigma = __expf(ldsf(base + SIGO + 4 * tid));
        const float sd = sigma * delta * dnorm;
        float x = sd;
        #pragma unroll
        for (int off = 1; off < 32; off <<= 1) {
            float v = __shfl_up_sync(0xffffffffu, x, off);
            if (lane >= off) x += v;
        }
        if (lane == 31) stsf(base + SCANW + 4 * wid, x);
        __syncthreads();
        float pre = 0.0f;
        #pragma unroll
        for (int w = 0; w < 4; ++w) if (w < wid) pre += ldsf(base + SCANW + 4 * w);
        const float excl = (x + pre) - sd;
        const float trans = __expf(-excl);
        const float alpha = 1.0f - __expf(-sd);
        const float wgt = trans * alpha * act;

        const float rC = 1.0f / (1.0f + __expf(-(ldsf(base + RGBO + tid * 16)     + p1)));
        const float gC = 1.0f / (1.0f + __expf(-(ldsf(base + RGBO + tid * 16 + 4) + p2)));
        const float bC = 1.0f / (1.0f + __expf(-(ldsf(base + RGBO + tid * 16 + 8) + p3)));

        float cr = wgt * rC, cg = wgt * gC, cb = wgt * bC, ca = wgt;
        #pragma unroll
        for (int off = 16; off > 0; off >>= 1) {
            cr += __shfl_xor_sync(0xffffffffu, cr, off);
            cg += __shfl_xor_sync(0xffffffffu, cg, off);
            cb += __shfl_xor_sync(0xffffffffu, cb, off);
            ca += __shfl_xor_sync(0xffffffffu, ca, off);
        }
        if (lane == 0) {
            stsf(base + PARTO + (wid * 4 + 0) * 4, cr);
            stsf(base + PARTO + (wid * 4 + 1) * 4, cg);
            stsf(base + PARTO + (wid * 4 + 2) * 4, cb);
            stsf(base + PARTO + (wid * 4 + 3) * 4, ca);
        }
        __syncthreads();
        if (tid == 0) {
            float4 o4 = make_float4(0.f, 0.f, 0.f, 0.f);
            #pragma unroll
            for (int w = 0; w < 4; ++w) {
                o4.x += ldsf(base + PARTO + (w * 4 + 0) * 4);
                o4.y += ldsf(base + PARTO + (w * 4 + 1) * 4);
                o4.z += ldsf(base + PARTO + (w * 4 + 2) * 4);
                o4.w += ldsf(base + PARTO + (w * 4 + 3) * 4);
            }
            *(float4*)(out + ray * 4) = o4;
        }
    }
}

extern "C" void kernel_launch(void* const* d_in, const int* in_sizes, int n_in,
                              void* d_out, int out_size) {
    const float* rays_o = (const float*)d_in[0];
    const float* rays_d = (const float*)d_in[1];
    const float* tnoise = (const float*)d_in[2];
    const float* aabb   = (const float*)d_in[3];
    const float* W1     = (const float*)d_in[4];
    const float* b1     = (const float*)d_in[5];
    const float* W2     = (const float*)d_in[6];
    const float* b2     = (const float*)d_in[7];
    const float* Wc1    = (const float*)d_in[8];
    const float* bc1    = (const float*)d_in[9];
    const float* Wc2    = (const float*)d_in[10];
    const float* bc2    = (const float*)d_in[11];
    float* out = (float*)d_out;

    k_setup<<<8, 256>>>(W1, W2, Wc1, Wc2, bc2);
    cudaFuncSetAttribute(nerf_mma8_kernel, cudaFuncAttributeMaxDynamicSharedMemorySize, SMEM_DYN);
    nerf_mma8_kernel<<<NBLK, 128, SMEM_DYN>>>(rays_o, rays_d, tnoise, aabb,
                                              b1, b2, bc1, Wc1, out);
}

// round 17
// speedup vs baseline: 1.5027x; 1.5027x over previous
#include <cuda_runtime.h>
#include <cuda_bf16.h>
#include <cstdint>

#define N_RAYS_C 16384
#define RAYS_PER_BLK 4
#define NBLK (N_RAYS_C / RAYS_PER_BLK)

// ---- smem byte offsets ----
#define A32HI 0
#define A32LO 10240
#define BOFF  20480
#define B1HI  (BOFF + 0)
#define B1LO  (BOFF + 5120)
#define B2HI  (BOFF + 10240)
#define B2LO  (BOFF + 12544)
#define B3HI  (BOFF + 14848)
#define B3LO  (BOFF + 19968)
#define B4HI  (BOFF + 25088)
#define B4LO  (BOFF + 26240)
#define BBYTES 27392
#define BIAS1 (BOFF + BBYTES)    // 64 f
#define BIAS2 (BIAS1 + 256)      // 16 f
#define BIAS3 (BIAS2 + 64)       // 64 f (per-ray fused bias)
#define WC1SH (BIAS3 + 256)      // 4 x 64 f  (Wc1 rows 15..18 cached)
#define SIGO  (WC1SH + 1024)     // 128 f
#define RGBO  (SIGO + 512)       // 128 x 16B
#define SCANW (RGBO + 2048)
#define PARTO (SCANW + 16)
#define SMEM_DYN 52736

#define S32 80
#define S64 144

__device__ __align__(16) unsigned char g_B[BBYTES];
__device__ float g_params[8];   // [1..3] = bc2

// ---- helpers ----
__device__ __forceinline__ uint32_t smem_u32(const void* p) {
    uint32_t a;
    asm("{ .reg .u64 t; cvta.to.shared.u64 t, %1; cvt.u32.u64 %0, t; }" : "=r"(a) : "l"(p));
    return a;
}
__device__ __forceinline__ void sts32(uint32_t a, uint32_t v) {
    asm volatile("st.shared.b32 [%0], %1;" :: "r"(a), "r"(v) : "memory");
}
__device__ __forceinline__ void sts128(uint32_t a, uint32_t v0, uint32_t v1,
                                       uint32_t v2, uint32_t v3) {
    asm volatile("st.shared.v4.b32 [%0], {%1,%2,%3,%4};"
                 :: "r"(a), "r"(v0), "r"(v1), "r"(v2), "r"(v3) : "memory");
}
__device__ __forceinline__ uint32_t lds32(uint32_t a) {
    uint32_t v; asm volatile("ld.shared.b32 %0, [%1];" : "=r"(v) : "r"(a)); return v;
}
__device__ __forceinline__ float ldsf(uint32_t a) { return __uint_as_float(lds32(a)); }
__device__ __forceinline__ void stsf(uint32_t a, float v) { sts32(a, __float_as_uint(v)); }

__device__ __forceinline__ void ldm_x4(uint32_t addr, uint32_t* r) {
    asm volatile("ldmatrix.sync.aligned.m8n8.x4.shared.b16 {%0,%1,%2,%3}, [%4];"
        : "=r"(r[0]), "=r"(r[1]), "=r"(r[2]), "=r"(r[3]) : "r"(addr));
}
__device__ __forceinline__ void ldm_x2(uint32_t addr, uint32_t* r) {
    asm volatile("ldmatrix.sync.aligned.m8n8.x2.shared.b16 {%0,%1}, [%2];"
        : "=r"(r[0]), "=r"(r[1]) : "r"(addr));
}

// pack f32 pair -> bf16x2 hi + residual lo; residual via bit-extract of hi
__device__ __forceinline__ void split2(float v0, float v1, uint32_t& hi, uint32_t& lo) {
    asm("cvt.rn.bf16x2.f32 %0, %1, %2;" : "=r"(hi) : "f"(v1), "f"(v0));
    const float r0 = v0 - __uint_as_float(hi << 16);
    const float r1 = v1 - __uint_as_float(hi & 0xffff0000u);
    asm("cvt.rn.bf16x2.f32 %0, %1, %2;" : "=r"(lo) : "f"(r1), "f"(r0));
}

__device__ __forceinline__ void mma16816(float* d,
        uint32_t a0, uint32_t a1, uint32_t a2, uint32_t a3,
        uint32_t b0, uint32_t b1) {
    asm volatile("mma.sync.aligned.m16n8k16.row.col.f32.bf16.bf16.f32 "
        "{%0,%1,%2,%3}, {%4,%5,%6,%7}, {%8,%9}, {%0,%1,%2,%3};"
        : "+f"(d[0]), "+f"(d[1]), "+f"(d[2]), "+f"(d[3])
        : "r"(a0), "r"(a1), "r"(a2), "r"(a3), "r"(b0), "r"(b1));
}
#define MMA(acc, a, b0, b1) mma16816(acc, (a)[0], (a)[1], (a)[2], (a)[3], b0, b1)

// ---- setup: build hi/lo weight image in [n][k]-padded layouts ----
__global__ void k_setup(const float* __restrict__ W1, const float* __restrict__ W2,
                        const float* __restrict__ Wc1, const float* __restrict__ Wc2,
                        const float* __restrict__ bc2) {
    const int tid = blockIdx.x * blockDim.x + threadIdx.x;
    if (tid == 0) { g_params[1] = bc2[0]; g_params[2] = bc2[1]; g_params[3] = bc2[2]; }
    const int n1 = 64 * 40, n2 = 16 * 72, n3 = 64 * 40, n4 = 8 * 72;
    for (int i = tid; i < n1 + n2 + n3 + n4; i += blockDim.x * gridDim.x) {
        float v; int hiOff, loOff;
        if (i < n1) {
            int n = i / 40, k = i % 40;
            v = (k < 27) ? W1[k * 64 + n] : 0.0f;
            hiOff = (B1HI - BOFF) + i * 2; loOff = (B1LO - BOFF) + i * 2;
        } else if (i < n1 + n2) {
            int j = i - n1, n = j / 72, k = j % 72;
            v = (k < 64) ? W2[k * 16 + n] : 0.0f;
            hiOff = (B2HI - BOFF) + j * 2; loOff = (B2LO - BOFF) + j * 2;
        } else if (i < n1 + n2 + n3) {
            int j = i - n1 - n2, n = j / 40, k = j % 40;
            v = (k >= 1 && k < 16) ? Wc1[(k - 1) * 64 + n] : 0.0f;   // ynm folded into bias
            hiOff = (B3HI - BOFF) + j * 2; loOff = (B3LO - BOFF) + j * 2;
        } else {
            int j = i - n1 - n2 - n3, n = j / 72, k = j % 72;
            v = (n < 3 && k < 64) ? Wc2[k * 3 + n] : 0.0f;
            hiOff = (B4HI - BOFF) + j * 2; loOff = (B4LO - BOFF) + j * 2;
        }
        __nv_bfloat16 hi = __float2bfloat16(v);
        __nv_bfloat16 lo = __float2bfloat16(v - __bfloat162float(hi));
        *(__nv_bfloat16*)(g_B + hiOff) = hi;
        *(__nv_bfloat16*)(g_B + loOff) = lo;
    }
}

// ---- render: 128 threads, 4 warps x M=32 rows, 4 rays sequential ----
__global__ void __launch_bounds__(128, 4) nerf_mma7_kernel(
    const float* __restrict__ rays_o, const float* __restrict__ rays_d,
    const float* __restrict__ tnoise, const float* __restrict__ aabb,
    const float* __restrict__ b1, const float* __restrict__ b2,
    const float* __restrict__ bc1, const float* __restrict__ Wc1,
    float* __restrict__ out) {
    extern __shared__ __align__(16) unsigned char sm[];
    const uint32_t base = smem_u32(sm);
    const int tid = threadIdx.x, lane = tid & 31, wid = tid >> 5;
    const int g = lane >> 2, tg = lane & 3;
    const int m0 = wid * 32;

    // prologue: weights + biases + Wc1 SH rows
    {
        const int4* src = (const int4*)g_B;
        int4* dst = (int4*)(sm + BOFF);
        for (int i = tid; i < BBYTES / 16; i += 128) dst[i] = src[i];
        if (tid < 64) stsf(base + BIAS1 + 4 * tid, b1[tid]);
        if (tid < 16) stsf(base + BIAS2 + 4 * tid, b2[tid]);
        for (int i = tid; i < 256; i += 128)
            stsf(base + WC1SH + 4 * i, Wc1[15 * 64 + i]);
    }
    const float ax0 = aabb[0], ay0 = aabb[1], az0 = aabb[2];
    const float ax1 = aabb[3], ay1 = aabb[4], az1 = aabb[5];
    const float p1 = g_params[1], p2 = g_params[2], p3 = g_params[3];
    __syncthreads();

    // per-lane ldmatrix address components
    const uint32_t arow = (uint32_t)((lane & 7) + ((lane >> 3) & 1) * 8);
    const uint32_t ak   = (uint32_t)(((lane >> 4) & 1) * 16);
    const uint32_t bn32 = (uint32_t)(((lane & 7) + ((lane >> 4) & 1) * 8) * S32
                                     + ((lane >> 3) & 1) * 16);
    const uint32_t bn64 = (uint32_t)(((lane & 7) + ((lane >> 4) & 1) * 8) * S64
                                     + ((lane >> 3) & 1) * 16);
    const uint32_t bn8  = (uint32_t)((lane & 7) * S64 + ((lane >> 3) & 1) * 16);

    for (int rr = 0; rr < RAYS_PER_BLK; ++rr) {
        const int ray = blockIdx.x * RAYS_PER_BLK + rr;

        // ---- ray setup (thread = sample row tid) ----
        const float ox = rays_o[3 * ray], oy = rays_o[3 * ray + 1], oz = rays_o[3 * ray + 2];
        const float dx = rays_d[3 * ray], dy = rays_d[3 * ray + 1], dz = rays_d[3 * ray + 2];
        const float ix = 1.0f / dx, iy = 1.0f / dy, iz = 1.0f / dz;
        const float t0x = (ax0 - ox) * ix, t1x = (ax1 - ox) * ix;
        const float t0y = (ay0 - oy) * iy, t1y = (ay1 - oy) * iy;
        const float t0z = (az0 - oz) * iz, t1z = (az1 - oz) * iz;
        float tn = fmaxf(fmaxf(fminf(t0x, t1x), fminf(t0y, t1y)), fminf(t0z, t1z));
        tn = fmaxf(tn, 0.0f);
        float tf = fminf(fminf(fmaxf(t0x, t1x), fmaxf(t0y, t1y)), fmaxf(t0z, t1z));
        float act;
        if (tf > tn) { act = 1.0f; } else { act = 0.0f; tn = 0.0f; tf = 0.0f; }
        const float span = tf - tn;
        const float dnorm = sqrtf(dx * dx + dy * dy + dz * dz);

        const float n0 = tnoise[tid * N_RAYS_C + ray];
        const float n1 = (tid < 127) ? tnoise[(tid + 1) * N_RAYS_C + ray] : 0.0f;
        const float ts  = tn + span * (((float)tid + n0) * (1.0f / 128.0f));
        const float ts1 = tn + span * (((float)tid + 1.0f + n1) * (1.0f / 128.0f));
        const float delta = (tid < 127) ? (ts1 - ts) : (tf * 10.0f - ts);

        const float idn = 1.0f / dnorm;
        const float c1 = 0.4886025119029199f;
        const float y0 = 0.28209479177387814f, y1 = c1 * dy * idn;
        const float y2 = c1 * dz * idn,        y3 = c1 * dx * idn;

        // per-ray fused color-layer bias: bc1 + ynm @ Wc1[15:19]  (fp32, from smem cache)
        if (tid < 64) {
            const float s = bc1[tid]
                          + y0 * ldsf(base + WC1SH + 4 * tid)
                          + y1 * ldsf(base + WC1SH + 4 * (64 + tid))
                          + y2 * ldsf(base + WC1SH + 4 * (128 + tid))
                          + y3 * ldsf(base + WC1SH + 4 * (192 + tid));
            stsf(base + BIAS3 + 4 * tid, s);
        }

        {   // posenc -> packed regs -> A32 row tid via 4+4 STS.128
            float e[28];
            const float px = ox + ts * dx, py = oy + ts * dy, pz = oz + ts * dz;
            const float xnx = 2.0f * (px - ax0) / (ax1 - ax0) - 1.0f;
            const float xny = 2.0f * (py - ay0) / (ay1 - ay0) - 1.0f;
            const float xnz = 2.0f * (pz - az0) / (az1 - az0) - 1.0f;
            e[0] = xnx; e[1] = xny; e[2] = xnz;
            float f = 3.14159265358979323846f;
            #pragma unroll
            for (int k = 0; k < 4; ++k) {
                float sx, cx, sy, cy, sz, cz;
                __sincosf(f * xnx, &sx, &cx);
                __sincosf(f * xny, &sy, &cy);
                __sincosf(f * xnz, &sz, &cz);
                e[3 + 6 * k + 0] = sx; e[3 + 6 * k + 1] = sy; e[3 + 6 * k + 2] = sz;
                e[6 + 6 * k + 0] = cx; e[6 + 6 * k + 1] = cy; e[6 + 6 * k + 2] = cz;
                f *= 2.0f;
            }
            e[27] = 0.0f;
            uint32_t hp[16], lp[16];
            #pragma unroll
            for (int p = 0; p < 14; ++p) split2(e[2 * p], e[2 * p + 1], hp[p], lp[p]);
            hp[14] = hp[15] = 0u; lp[14] = lp[15] = 0u;   // cols 28..31 zero
            const uint32_t rb = (uint32_t)tid * S32;
            #pragma unroll
            for (int q = 0; q < 4; ++q) {
                sts128(base + A32HI + rb + 16 * q, hp[4 * q], hp[4 * q + 1], hp[4 * q + 2], hp[4 * q + 3]);
                sts128(base + A32LO + rb + 16 * q, lp[4 * q], lp[4 * q + 1], lp[4 * q + 2], lp[4 * q + 3]);
            }
        }
        __syncthreads();   // A32 + BIAS3 visible to all warps

        float acc[2][8][4];
        // ---- stage 1: posenc @ W1 (K32,N64) ----
        {
            uint32_t a1h[2][2][4], a1l[2][2][4];
            #pragma unroll
            for (int mt = 0; mt < 2; ++mt) {
                const uint32_t ao = (uint32_t)((m0 + 16 * mt) * S32) + arow * S32 + ak;
                #pragma unroll
                for (int kb = 0; kb < 2; ++kb) {
                    ldm_x4(base + A32HI + ao + kb * 32, a1h[mt][kb]);
                    ldm_x4(base + A32LO + ao + kb * 32, a1l[mt][kb]);
                }
            }
            #pragma unroll
            for (int mt = 0; mt < 2; ++mt)
                #pragma unroll
                for (int nt = 0; nt < 8; ++nt)
                    acc[mt][nt][0] = acc[mt][nt][1] = acc[mt][nt][2] = acc[mt][nt][3] = 0.f;
            #pragma unroll
            for (int np = 0; np < 4; ++np) {
                #pragma unroll
                for (int kb = 0; kb < 2; ++kb) {
                    uint32_t bh[4], bl[4];
                    const uint32_t bo = bn32 + (uint32_t)(np * 16 * S32) + kb * 32;
                    ldm_x4(base + B1HI + bo, bh);
                    #pragma unroll
                    for (int mt = 0; mt < 2; ++mt) {
                        MMA(acc[mt][2 * np],     a1h[mt][kb], bh[0], bh[1]);
                        MMA(acc[mt][2 * np + 1], a1h[mt][kb], bh[2], bh[3]);
                        MMA(acc[mt][2 * np],     a1l[mt][kb], bh[0], bh[1]);
                        MMA(acc[mt][2 * np + 1], a1l[mt][kb], bh[2], bh[3]);
                    }
                    ldm_x4(base + B1LO + bo, bl);
                    #pragma unroll
                    for (int mt = 0; mt < 2; ++mt) {
                        MMA(acc[mt][2 * np],     a1h[mt][kb], bl[0], bl[1]);
                        MMA(acc[mt][2 * np + 1], a1h[mt][kb], bl[2], bl[3]);
                    }
                }
            }
        }

        // ---- epilogue 1: bias+relu -> stage2 A frags (registers) ----
        uint32_t f2h[2][4][4], f2l[2][4][4];
        #pragma unroll
        for (int nt = 0; nt < 8; ++nt) {
            const int c = nt * 8 + tg * 2;
            const float bb0 = ldsf(base + BIAS1 + 4 * c);
            const float bb1 = ldsf(base + BIAS1 + 4 * c + 4);
            const int kb = nt >> 1, hb = (nt & 1) * 2;
            #pragma unroll
            for (int mt = 0; mt < 2; ++mt) {
                float* d = acc[mt][nt];
                split2(fmaxf(d[0] + bb0, 0.f), fmaxf(d[1] + bb1, 0.f),
                       f2h[mt][kb][hb], f2l[mt][kb][hb]);
                split2(fmaxf(d[2] + bb0, 0.f), fmaxf(d[3] + bb1, 0.f),
                       f2h[mt][kb][hb + 1], f2l[mt][kb][hb + 1]);
            }
        }

        // ---- stage 2: h @ W2 (K64,N16) ----
        #pragma unroll
        for (int mt = 0; mt < 2; ++mt)
            #pragma unroll
            for (int nt = 0; nt < 2; ++nt)
                acc[mt][nt][0] = acc[mt][nt][1] = acc[mt][nt][2] = acc[mt][nt][3] = 0.f;
        #pragma unroll
        for (int kb = 0; kb < 4; ++kb) {
            uint32_t bh[4], bl[4];
            ldm_x4(base + B2HI + bn64 + kb * 32, bh);
            #pragma unroll
            for (int mt = 0; mt < 2; ++mt) {
                MMA(acc[mt][0], f2h[mt][kb], bh[0], bh[1]);
                MMA(acc[mt][1], f2h[mt][kb], bh[2], bh[3]);
                MMA(acc[mt][0], f2l[mt][kb], bh[0], bh[1]);
                MMA(acc[mt][1], f2l[mt][kb], bh[2], bh[3]);
            }
            ldm_x4(base + B2LO + bn64 + kb * 32, bl);
            #pragma unroll
            for (int mt = 0; mt < 2; ++mt) {
                MMA(acc[mt][0], f2h[mt][kb], bl[0], bl[1]);
                MMA(acc[mt][1], f2h[mt][kb], bl[2], bl[3]);
            }
        }

        // ---- epilogue 2: sigma + stage3 A frags (K=16) ----
        uint32_t a3h[2][4], a3l[2][4];
        #pragma unroll
        for (int nt = 0; nt < 2; ++nt) {
            const int c = nt * 8 + tg * 2;
            const float bb0 = ldsf(base + BIAS2 + 4 * c);
            const float bb1 = ldsf(base + BIAS2 + 4 * c + 4);
            const int hb = nt * 2;
            #pragma unroll
            for (int mt = 0; mt < 2; ++mt) {
                float* d = acc[mt][nt];
                const float v0 = d[0] + bb0, v1 = d[1] + bb1;
                const float v2 = d[2] + bb0, v3 = d[3] + bb1;
                split2(v0, v1, a3h[mt][hb], a3l[mt][hb]);
                split2(v2, v3, a3h[mt][hb + 1], a3l[mt][hb + 1]);
                if (nt == 0 && tg == 0) {
                    stsf(base + SIGO + 4 * (m0 + 16 * mt + g), v0);
                    stsf(base + SIGO + 4 * (m0 + 16 * mt + g + 8), v2);
                }
            }
        }

        // ---- stage 3: feat @ Wc1[0:15] (K16,N64) ----
        #pragma unroll
        for (int mt = 0; mt < 2; ++mt)
            #pragma unroll
            for (int nt = 0; nt < 8; ++nt)
                acc[mt][nt][0] = acc[mt][nt][1] = acc[mt][nt][2] = acc[mt][nt][3] = 0.f;
        #pragma unroll
        for (int np = 0; np < 4; ++np) {
            uint32_t bh[4], bl[4];
            const uint32_t bo = bn32 + (uint32_t)(np * 16 * S32);
            ldm_x4(base + B3HI + bo, bh);
            #pragma unroll
            for (int mt = 0; mt < 2; ++mt) {
                MMA(acc[mt][2 * np],     a3h[mt], bh[0], bh[1]);
                MMA(acc[mt][2 * np + 1], a3h[mt], bh[2], bh[3]);
                MMA(acc[mt][2 * np],     a3l[mt], bh[0], bh[1]);
                MMA(acc[mt][2 * np + 1], a3l[mt], bh[2], bh[3]);
            }
            ldm_x4(base + B3LO + bo, bl);
            #pragma unroll
            for (int mt = 0; mt < 2; ++mt) {
                MMA(acc[mt][2 * np],     a3h[mt], bl[0], bl[1]);
                MMA(acc[mt][2 * np + 1], a3h[mt], bl[2], bl[3]);
            }
        }

        // ---- epilogue 3: (per-ray fused bias)+relu -> stage4 A frags ----
        #pragma unroll
        for (int nt = 0; nt < 8; ++nt) {
            const int c = nt * 8 + tg * 2;
            const float bb0 = ldsf(base + BIAS3 + 4 * c);
            const float bb1 = ldsf(base + BIAS3 + 4 * c + 4);
            const int kb = nt >> 1, hb = (nt & 1) * 2;
            #pragma unroll
            for (int mt = 0; mt < 2; ++mt) {
                float* d = acc[mt][nt];
                split2(fmaxf(d[0] + bb0, 0.f), fmaxf(d[1] + bb1, 0.f),
                       f2h[mt][kb][hb], f2l[mt][kb][hb]);
                split2(fmaxf(d[2] + bb0, 0.f), fmaxf(d[3] + bb1, 0.f),
                       f2h[mt][kb][hb + 1], f2l[mt][kb][hb + 1]);
            }
        }

        // ---- stage 4: hc @ Wc2 (K64,N8) ----
        float a4[2][4];
        a4[0][0] = a4[0][1] = a4[0][2] = a4[0][3] = 0.f;
        a4[1][0] = a4[1][1] = a4[1][2] = a4[1][3] = 0.f;
        #pragma unroll
        for (int kb = 0; kb < 4; ++kb) {
            uint32_t bh[2], bl[2];
            ldm_x2(base + B4HI + bn8 + kb * 32, bh);
            #pragma unroll
            for (int mt = 0; mt < 2; ++mt) {
                MMA(a4[mt], f2h[mt][kb], bh[0], bh[1]);
                MMA(a4[mt], f2l[mt][kb], bh[0], bh[1]);
            }
            ldm_x2(base + B4LO + bn8 + kb * 32, bl);
            #pragma unroll
            for (int mt = 0; mt < 2; ++mt)
                MMA(a4[mt], f2h[mt][kb], bl[0], bl[1]);
        }
        if (tg < 2) {
            #pragma unroll
            for (int mt = 0; mt < 2; ++mt) {
                const int rA = m0 + 16 * mt + g, rB = rA + 8;
                stsf(base + RGBO + rA * 16 + tg * 8,     a4[mt][0]);
                stsf(base + RGBO + rA * 16 + tg * 8 + 4, a4[mt][1]);
                stsf(base + RGBO + rB * 16 + tg * 8,     a4[mt][2]);
                stsf(base + RGBO + rB * 16 + tg * 8 + 4, a4[mt][3]);
            }
        }
        __syncthreads();

        // ---- transmittance scan + composite (thread = sample tid) ----
        const float sigma = __expf(ldsf(base + SIGO + 4 * tid));
        const float sd = sigma * delta * dnorm;
        float x = sd;
        #pragma unroll
        for (int off = 1; off < 32; off <<= 1) {
            float v = __shfl_up_sync(0xffffffffu, x, off);
            if (lane >= off) x += v;
        }
        if (lane == 31) stsf(base + SCANW + 4 * wid, x);
        __syncthreads();
        float pre = 0.0f;
        #pragma unroll
        for (int w = 0; w < 4; ++w) if (w < wid) pre += ldsf(base + SCANW + 4 * w);
        const float excl = (x + pre) - sd;
        const float trans = __expf(-excl);
        const float alpha = 1.0f - __expf(-sd);
        const float wgt = trans * alpha * act;

        const float rC = 1.0f / (1.0f + __expf(-(ldsf(base + RGBO + tid * 16)     + p1)));
        const float gC = 1.0f / (1.0f + __expf(-(ldsf(base + RGBO + tid * 16 + 4) + p2)));
        const float bC = 1.0f / (1.0f + __expf(-(ldsf(base + RGBO + tid * 16 + 8) + p3)));

        float cr = wgt * rC, cg = wgt * gC, cb = wgt * bC, ca = wgt;
        #pragma unroll
        for (int off = 16; off > 0; off >>= 1) {
            cr += __shfl_xor_sync(0xffffffffu, cr, off);
            cg += __shfl_xor_sync(0xffffffffu, cg, off);
            cb += __shfl_xor_sync(0xffffffffu, cb, off);
            ca += __shfl_xor_sync(0xffffffffu, ca, off);
        }
        if (lane == 0) {
            stsf(base + PARTO + (wid * 4 + 0) * 4, cr);
            stsf(base + PARTO + (wid * 4 + 1) * 4, cg);
            stsf(base + PARTO + (wid * 4 + 2) * 4, cb);
            stsf(base + PARTO + (wid * 4 + 3) * 4, ca);
        }
        __syncthreads();
        if (tid == 0) {
            float4 o4 = make_float4(0.f, 0.f, 0.f, 0.f);
            #pragma unroll
            for (int w = 0; w < 4; ++w) {
                o4.x += ldsf(base + PARTO + (w * 4 + 0) * 4);
                o4.y += ldsf(base + PARTO + (w * 4 + 1) * 4);
                o4.z += ldsf(base + PARTO + (w * 4 + 2) * 4);
                o4.w += ldsf(base + PARTO + (w * 4 + 3) * 4);
            }
            *(float4*)(out + ray * 4) = o4;
        }
        __syncthreads();
    }
}

extern "C" void kernel_launch(void* const* d_in, const int* in_sizes, int n_in,
                              void* d_out, int out_size) {
    const float* rays_o = (const float*)d_in[0];
    const float* rays_d = (const float*)d_in[1];
    const float* tnoise = (const float*)d_in[2];
    const float* aabb   = (const float*)d_in[3];
    const float* W1     = (const float*)d_in[4];
    const float* b1     = (const float*)d_in[5];
    const float* W2     = (const float*)d_in[6];
    const float* b2     = (const float*)d_in[7];
    const float* Wc1    = (const float*)d_in[8];
    const float* bc1    = (const float*)d_in[9];
    const float* Wc2    = (const float*)d_in[10];
    const float* bc2    = (const float*)d_in[11];
    float* out = (float*)d_out;

    k_setup<<<8, 256>>>(W1, W2, Wc1, Wc2, bc2);
    cudaFuncSetAttribute(nerf_mma7_kernel, cudaFuncAttributeMaxDynamicSharedMemorySize, SMEM_DYN);
    nerf_mma7_kernel<<<NBLK, 128, SMEM_DYN>>>(rays_o, rays_d, tnoise, aabb,
                                              b1, b2, bc1, Wc1, out);
}